// round 2
// baseline (speedup 1.0000x reference)
#include <cuda_runtime.h>
#include <cstdint>

#define SEQ   4096
#define EMB   300
#define K_IN  600      // 2*EMB
#define HID   500
#define JPAD  512      // padded hidden
#define GPAD  2048     // padded gate rows (4*JPAD)
#define NCTA  64       // recurrence CTAs (one wave, guaranteed co-resident)
#define CTHR  256      // threads per recurrence CTA (8 warps = 8 hidden units)

// ---------------- scratch (static device globals; no allocation) -----------
__device__ float g_X[(size_t)SEQ * K_IN];          // gathered inputs  [4096][600]
__device__ float g_pre[(size_t)SEQ * GPAD];        // pre-activations, remapped
__device__ float g_hbuf[2][JPAD];                  // double-buffered h broadcast
__device__ int   g_flag[NCTA];                     // per-CTA monotonic step flags

// ---------------- fast activations (MUFU ex2/rcp) --------------------------
__device__ __forceinline__ float fex2(float x){ float y; asm("ex2.approx.f32 %0,%1;":"=f"(y):"f"(x)); return y; }
__device__ __forceinline__ float frcp(float x){ float y; asm("rcp.approx.f32 %0,%1;":"=f"(y):"f"(x)); return y; }
__device__ __forceinline__ float fsig (float x){ return frcp(1.0f + fex2(-1.44269504f * x)); }
__device__ __forceinline__ float ftanh(float x){ float e = fex2(2.88539008f * x); return 1.0f - 2.0f * frcp(e + 1.0f); }

__device__ __forceinline__ unsigned long long pack2(float a, float b){
    unsigned long long r; asm("mov.b64 %0,{%1,%2};" : "=l"(r) : "f"(a), "f"(b)); return r;
}
__device__ __forceinline__ void unpack2(unsigned long long v, float& a, float& b){
    asm("mov.b64 {%0,%1},%2;" : "=f"(a), "=f"(b) : "l"(v));
}
__device__ __forceinline__ void fma2(unsigned long long& acc, unsigned long long a, unsigned long long b){
    asm("fma.rn.f32x2 %0, %1, %2, %0;" : "+l"(acc) : "l"(a), "l"(b));
}

// ---------------- kernel 1: reset per-CTA flags -----------------------------
__global__ void k_reset()
{
    if (threadIdx.x < NCTA) g_flag[threadIdx.x] = 0;
}

// ---------------- kernel 2: embedding gather + concat -----------------------
__global__ void k_gather(const int* __restrict__ words, const int* __restrict__ labels,
                         const float* __restrict__ ew,  const float* __restrict__ ee)
{
    int id = blockIdx.x * blockDim.x + threadIdx.x;
    int t = id / K_IN;
    int k = id - t * K_IN;
    float v = (k < EMB) ? ew[(size_t)words[t]  * EMB + k]
                        : ee[(size_t)labels[t] * EMB + (k - EMB)];
    g_X[id] = v;
}

// ---------------- kernel 3: pre = X @ W_ih^T + (b_ih + b_hh), remapped ------
// Global gate row R in [0,2048):
//   blk = R>>5, rl = R&31, uu = rl>>2 (unit within CTA), g = rl&3 (gate i,f,g,o)
//   hidden unit j = 8*blk + uu ; W row = g*HID + j. Padded (j>=HID) rows -> 0.
// This makes the 4 gates of one unit CONTIGUOUS (LDG.128 in the recurrence).
__global__ void __launch_bounds__(256) k_gemm(const float* __restrict__ W,
                                              const float* __restrict__ bi,
                                              const float* __restrict__ bh)
{
    __shared__ float xs[8][64];
    __shared__ float ws[8][68];

    int t0 = blockIdx.x * 64;
    int R0 = blockIdx.y * 64;
    int tid = threadIdx.x;
    int tx = tid & 15;
    int ty = tid >> 4;

    float acc[4][4];
#pragma unroll
    for (int i = 0; i < 4; i++)
#pragma unroll
        for (int j = 0; j < 4; j++) acc[i][j] = 0.0f;

    for (int k0 = 0; k0 < K_IN; k0 += 8) {
#pragma unroll
        for (int p = 0; p < 2; p++) {
            int e  = tid + p * 256;
            int kk = e >> 6;
            int rr = e & 63;
            int R = R0 + rr;
            int g  = R & 3;
            int j  = ((R >> 5) << 3) | ((R >> 2) & 7);
            float wv = 0.0f;
            if (j < HID) wv = W[(size_t)(g * HID + j) * K_IN + (k0 + kk)];
            ws[kk][rr] = wv;
            xs[kk][rr] = g_X[(size_t)(t0 + rr) * K_IN + (k0 + kk)];
        }
        __syncthreads();
#pragma unroll
        for (int kk = 0; kk < 8; kk++) {
            float a[4], x[4];
#pragma unroll
            for (int i = 0; i < 4; i++) a[i] = ws[kk][ty + 16 * i];
#pragma unroll
            for (int j = 0; j < 4; j++) x[j] = xs[kk][tx + 16 * j];
#pragma unroll
            for (int i = 0; i < 4; i++)
#pragma unroll
                for (int j = 0; j < 4; j++) acc[i][j] += a[i] * x[j];
        }
        __syncthreads();
    }

#pragma unroll
    for (int i = 0; i < 4; i++) {
        int R = R0 + ty + 16 * i;
        int g  = R & 3;
        int j  = ((R >> 5) << 3) | ((R >> 2) & 7);
        bool valid = (j < HID);
        float bb = valid ? (bi[g * HID + j] + bh[g * HID + j]) : 0.0f;
#pragma unroll
        for (int jx = 0; jx < 4; jx++) {
            int t = t0 + tx + 16 * jx;
            g_pre[(size_t)t * GPAD + R] = valid ? (acc[i][jx] + bb) : 0.0f;
        }
    }
}

// ---------------- kernel 4: persistent LSTM recurrence + final FC -----------
// 64 CTAs x 256 threads. Warp uu (0..7) of CTA blk owns hidden unit
// j = 8*blk + uu and computes ALL FOUR gates of that unit.
// Lane covers packed k-pairs: k = 2*lane + 64*m, m<8 (512 total).
// Per step: poll 64 flags -> coalesced LDG.64.cg of h from L2 -> 32 f32x2 FMA
// -> 4x warp reduce -> lane0 cell update -> STG.cg h -> st.release flag.
__global__ void __launch_bounds__(CTHR, 1)
k_lstm(const float* __restrict__ Whh, const float* __restrict__ fcw,
       const float* __restrict__ fcb, float* __restrict__ out)
{
    const int tid  = threadIdx.x;
    const int blk  = blockIdx.x;
    const int uu   = tid >> 5;          // warp id = hidden unit within CTA
    const int lane = tid & 31;
    const int j    = blk * 8 + uu;      // global hidden unit

    // register-resident W_hh: 4 gates x 8 packed pairs (zeros for padding)
    unsigned long long w2[4][8];
#pragma unroll
    for (int g = 0; g < 4; g++) {
#pragma unroll
        for (int m = 0; m < 8; m++) {
            int k = 2 * lane + 64 * m;
            float a = 0.0f, b = 0.0f;
            if (j < HID) {
                const float* row = Whh + (size_t)(g * HID + j) * HID;
                if (k     < HID) a = row[k];
                if (k + 1 < HID) b = row[k + 1];
            }
            w2[g][m] = pack2(a, b);
        }
    }

    float c = 0.0f;                     // cell state (lane 0 authoritative)
    const float* preB = g_pre + (size_t)blk * 32 + uu * 4;

#pragma unroll 1
    for (int t = 0; t < SEQ; t++) {
        // prefetch this step's 4 gate pre-activations (issues before the poll)
        float4 pv = make_float4(0.f, 0.f, 0.f, 0.f);
        if (lane == 0)
            pv = __ldg((const float4*)(preB + (size_t)t * GPAD));

        unsigned long long acc2[4] = {0ull, 0ull, 0ull, 0ull};

        if (t > 0) {
            // wait for every CTA to have published h(t)
            if (tid < NCTA) {
                int v;
                do {
                    asm volatile("ld.global.acquire.gpu.b32 %0, [%1];"
                                 : "=r"(v) : "l"(&g_flag[tid]) : "memory");
                } while (v < t);
            }
            __syncthreads();

            // coalesced L2 loads of h(t): lane -> k = 2*lane + 64*m
            const float2* hb = (const float2*)g_hbuf[t & 1];
            unsigned long long h2[8];
#pragma unroll
            for (int m = 0; m < 8; m++) {
                float2 hv = __ldcg(&hb[lane + 32 * m]);
                h2[m] = pack2(hv.x, hv.y);
            }
#pragma unroll
            for (int m = 0; m < 8; m++)
#pragma unroll
                for (int g = 0; g < 4; g++)
                    fma2(acc2[g], w2[g][m], h2[m]);
        }

        // reduce: pack -> scalar per gate, then 5-stage butterfly (4-way ILP)
        float s[4];
#pragma unroll
        for (int g = 0; g < 4; g++) {
            float lo, hi; unpack2(acc2[g], lo, hi);
            s[g] = lo + hi;
        }
#pragma unroll
        for (int d = 16; d >= 1; d >>= 1)
#pragma unroll
            for (int g = 0; g < 4; g++)
                s[g] += __shfl_xor_sync(0xffffffffu, s[g], d);

        const int nb = (t + 1) & 1;
        if (lane == 0) {
            float gi = fsig (s[0] + pv.x);
            float gf = fsig (s[1] + pv.y);
            float gg = ftanh(s[2] + pv.z);
            float go = fsig (s[3] + pv.w);
            c = gf * c + gi * gg;
            float h = go * ftanh(c);
            __stcg(&g_hbuf[nb][j], h);
        }
        __syncthreads();                 // all 8 units' h stores issued
        if (tid == 0) {
            __threadfence();             // make h(t+1) globally visible
            asm volatile("st.global.release.gpu.b32 [%0], %1;"
                         :: "l"(&g_flag[blk]), "r"(t + 1) : "memory");
        }
    }

    // ---------------- final FC: out[20] = fc_w @ h(SEQ) + fc_b (CTA 0) ------
    if (blk == 0) {
        if (tid < NCTA) {
            int v;
            do {
                asm volatile("ld.global.acquire.gpu.b32 %0, [%1];"
                             : "=r"(v) : "l"(&g_flag[tid]) : "memory");
            } while (v < SEQ);
        }
        __syncthreads();

        const float* hL = g_hbuf[SEQ & 1];   // h after 4096 steps
#pragma unroll 1
        for (int o = uu; o < 20; o += 8) {
            float a = 0.0f;
#pragma unroll
            for (int m = 0; m < 16; m++) {
                int k = lane + 32 * m;
                if (k < HID) a += fcw[(size_t)o * HID + k] * __ldcg(&hL[k]);
            }
#pragma unroll
            for (int d = 16; d >= 1; d >>= 1)
                a += __shfl_xor_sync(0xffffffffu, a, d);
            if (lane == 0) out[o] = a + fcb[o];
        }
    }
}

// ---------------- launch ----------------------------------------------------
extern "C" void kernel_launch(void* const* d_in, const int* in_sizes, int n_in,
                              void* d_out, int out_size)
{
    const int*   words  = (const int*)  d_in[0];
    const int*   labels = (const int*)  d_in[1];
    const float* ew     = (const float*)d_in[2];
    const float* ee     = (const float*)d_in[3];
    const float* W_ih   = (const float*)d_in[4];
    const float* W_hh   = (const float*)d_in[5];
    const float* b_ih   = (const float*)d_in[6];
    const float* b_hh   = (const float*)d_in[7];
    const float* fc_w   = (const float*)d_in[8];
    const float* fc_b   = (const float*)d_in[9];
    float* out = (float*)d_out;

    k_reset<<<1, 64>>>();
    k_gather<<<(SEQ * K_IN) / 1024, 1024>>>(words, labels, ew, ee);
    k_gemm<<<dim3(SEQ / 64, GPAD / 64), 256>>>(W_ih, b_ih, b_hh);
    k_lstm<<<NCTA, CTHR>>>(W_hh, fc_w, fc_b, out);
}